// round 3
// baseline (speedup 1.0000x reference)
#include <cuda_runtime.h>

#define NT 256
#define HDIM 64
#define OUTS 20

// ---------------- f32x2 packed-FMA helpers (sm_100+) ----------------
__device__ __forceinline__ unsigned long long pk2(float lo, float hi) {
    unsigned long long r;
    asm("mov.b64 %0, {%1, %2};" : "=l"(r) : "f"(lo), "f"(hi));
    return r;
}
__device__ __forceinline__ float hadd2(unsigned long long v) {
    float lo, hi;
    asm("mov.b64 {%0, %1}, %2;" : "=f"(lo), "=f"(hi) : "l"(v));
    return lo + hi;
}
__device__ __forceinline__ unsigned long long ffma2(unsigned long long a,
                                                    unsigned long long b,
                                                    unsigned long long c) {
    unsigned long long d;
    asm("fma.rn.f32x2 %0, %1, %2, %3;" : "=l"(d) : "l"(a), "l"(b), "l"(c));
    return d;
}

__device__ __forceinline__ float fsigmoid(float x) {
    float e = __expf(-x);                 // large -x -> inf -> result 0 (safe)
    return __fdividef(1.0f, 1.0f + e);
}
__device__ __forceinline__ float ftanh(float x) {
    float a = fabsf(x);
    float e = __expf(-2.0f * a);          // in (0,1]; no overflow
    float t = __fdividef(1.0f - e, 1.0f + e);
    return copysignf(t, x);
}

// Shared weight region layout (in floats):
//   [0,     12288)  Whh   row-major 192 x 64
//   [12288, 13056)  Wih   row-major 192 x 4
//   [13056, 13184)  bRZ   = bih + bhh for rows 0..127 (r and z gates)
//   [13184, 13248)  bIN   = bih rows 128..191 (n gate, input side)
//   [13248, 13312)  bHN   = bhh rows 128..191 (n gate, hidden side, inside r*(.))
//   [13312, 13568)  linW  4 x 64 (decoder phase only)
//   [13568, 13572)  linb
#define SW_FLOATS 13600              // padded, 16B aligned
#define HBUF_FLOATS (HDIM * NT)      // 16384 floats per h buffer

__device__ __forceinline__ void load_weights(float* sw,
                                             const float* Wih, const float* Whh,
                                             const float* bih, const float* bhh,
                                             const float* linW, const float* linb,
                                             bool with_lin, int tid) {
    float4* sw4 = (float4*)sw;
    const float4* whh4 = (const float4*)Whh;
    for (int i = tid; i < 12288 / 4; i += NT) sw4[i] = whh4[i];
    const float4* wih4 = (const float4*)Wih;
    for (int i = tid; i < 768 / 4; i += NT) ((float4*)(sw + 12288))[i] = wih4[i];
    for (int i = tid; i < 128; i += NT) sw[13056 + i] = bih[i] + bhh[i];
    for (int i = tid; i < 64; i += NT) {
        sw[13184 + i] = bih[128 + i];
        sw[13248 + i] = bhh[128 + i];
    }
    if (with_lin) {
        for (int i = tid; i < 256 / 4; i += NT)
            ((float4*)(sw + 13312))[i] = ((const float4*)linW)[i];
        if (tid < 4) sw[13568 + tid] = linb[tid];
    }
}

// One GRU step for this thread's batch element. h stored per-thread in shared,
// float4-chunk layout: chunk c (h[4c..4c+3]) at float4 index c*NT + tid.
// Returns (DEC only) x = h_new @ linW.T + linb  (px and offset added by caller).
template <bool DEC>
__device__ __forceinline__ float4 gru_step(const float* sw,
                                           const float* hcur, float* hnext,
                                           int tid, float4 px) {
    const char* whh = (const char*)sw;                 // row stride 256 B
    const float4* wih4 = (const float4*)(sw + 12288);  // 192 rows of float4
    const float* bRZ = sw + 13056;
    const float* bIN = sw + 13184;
    const float* bHN = sw + 13248;
    const float* linW = sw + 13312;
    const float* linb = sw + 13568;

    float xs0 = 0.f, xs1 = 0.f, xs2 = 0.f, xs3 = 0.f;
    if (DEC) { xs0 = linb[0]; xs1 = linb[1]; xs2 = linb[2]; xs3 = linb[3]; }

    const ulonglong2* hc2 = (const ulonglong2*)hcur;
    const float4* hc4 = (const float4*)hcur;
    float4* hn4 = (float4*)hnext;

#pragma unroll 1
    for (int tile = 0; tile < 4; ++tile) {
        unsigned long long ar[16], az[16], an[16];
#pragma unroll
        for (int jj = 0; jj < 16; ++jj) {
            int j = tile * 16 + jj;
            ar[jj] = pk2(bRZ[j], 0.f);
            az[jj] = pk2(bRZ[64 + j], 0.f);
            an[jj] = pk2(bHN[j], 0.f);
        }
        const char* wtile = whh + tile * 16 * 256;
#pragma unroll 2
        for (int c = 0; c < 16; ++c) {                 // k-chunks of 4
            ulonglong2 h2 = hc2[c * NT + tid];
            const char* wp0 = wtile + c * 16;
#pragma unroll
            for (int jj = 0; jj < 16; ++jj) {
                const char* p = wp0 + jj * 256;
                ulonglong2 wr = *(const ulonglong2*)(p);
                ulonglong2 wz = *(const ulonglong2*)(p + 16384);
                ulonglong2 wn = *(const ulonglong2*)(p + 32768);
                ar[jj] = ffma2(h2.x, wr.x, ar[jj]);
                ar[jj] = ffma2(h2.y, wr.y, ar[jj]);
                az[jj] = ffma2(h2.x, wz.x, az[jj]);
                az[jj] = ffma2(h2.y, wz.y, az[jj]);
                an[jj] = ffma2(h2.x, wn.x, an[jj]);
                an[jj] = ffma2(h2.y, wn.y, an[jj]);
            }
        }
        // old h for this tile (16 values)
        float hold[16];
#pragma unroll
        for (int q = 0; q < 4; ++q) {
            float4 hv = hc4[(tile * 4 + q) * NT + tid];
            hold[q * 4 + 0] = hv.x; hold[q * 4 + 1] = hv.y;
            hold[q * 4 + 2] = hv.z; hold[q * 4 + 3] = hv.w;
        }
        float hnv[4];
#pragma unroll
        for (int jj = 0; jj < 16; ++jj) {
            int j = tile * 16 + jj;
            float ghr = hadd2(ar[jj]);
            float ghz = hadd2(az[jj]);
            float ghn = hadd2(an[jj]);
            float4 wir = wih4[j];
            float4 wiz = wih4[64 + j];
            float4 win = wih4[128 + j];
            float gr = ghr + px.x * wir.x + px.y * wir.y + px.z * wir.z + px.w * wir.w;
            float gz = ghz + px.x * wiz.x + px.y * wiz.y + px.z * wiz.z + px.w * wiz.w;
            float gin = bIN[j] + px.x * win.x + px.y * win.y + px.z * win.z + px.w * win.w;
            float r = fsigmoid(gr);
            float z = fsigmoid(gz);
            float n = ftanh(gin + r * ghn);
            float hnew = n + z * (hold[jj] - n);
            hnv[jj & 3] = hnew;
            if (DEC) {
                xs0 = fmaf(hnew, linW[j], xs0);
                xs1 = fmaf(hnew, linW[64 + j], xs1);
                xs2 = fmaf(hnew, linW[128 + j], xs2);
                xs3 = fmaf(hnew, linW[192 + j], xs3);
            }
            if ((jj & 3) == 3)
                hn4[(tile * 4 + (jj >> 2)) * NT + tid] =
                    make_float4(hnv[0], hnv[1], hnv[2], hnv[3]);
        }
    }
    return make_float4(xs0, xs1, xs2, xs3);
}

__global__ void __launch_bounds__(NT, 1)
gru_encdec_kernel(const float* __restrict__ seq,
                  const float* __restrict__ enc_Wih, const float* __restrict__ enc_Whh,
                  const float* __restrict__ enc_bih, const float* __restrict__ enc_bhh,
                  const float* __restrict__ dec_Wih, const float* __restrict__ dec_Whh,
                  const float* __restrict__ dec_bih, const float* __restrict__ dec_bhh,
                  const float* __restrict__ lin_W, const float* __restrict__ lin_b,
                  float* __restrict__ out) {
    extern __shared__ float smem[];
    float* sw = smem;
    float* hA = smem + SW_FLOATS;
    float* hB = hA + HBUF_FLOATS;
    const int tid = threadIdx.x;
    const int b = blockIdx.x * NT + tid;

    load_weights(sw, enc_Wih, enc_Whh, enc_bih, enc_bhh, nullptr, nullptr, false, tid);
#pragma unroll
    for (int c = 0; c < 16; ++c)
        ((float4*)hA)[c * NT + tid] = make_float4(0.f, 0.f, 0.f, 0.f);
    __syncthreads();

    const float4* seqb = (const float4*)seq + (size_t)b * 51;
    float4 xc = seqb[0];
    float* hc = hA;
    float* hx = hB;
    float4 px = make_float4(0.f, 0.f, 0.f, 0.f);

#pragma unroll 1
    for (int t = 0; t < 50; ++t) {
        float4 xn = seqb[t + 1];
        px = make_float4(xn.x - xc.x, xn.y - xc.y, xn.z - xc.z, xn.w - xc.w);
        xc = xn;
        gru_step<false>(sw, hc, hx, tid, px);
        float* tmp = hc; hc = hx; hx = tmp;
    }
    float4 off = xc;  // input_seq[:, 50, :]

    __syncthreads();  // all threads done with encoder weights
    load_weights(sw, dec_Wih, dec_Whh, dec_bih, dec_bhh, lin_W, lin_b, true, tid);
    __syncthreads();

    float4* outb = (float4*)out + (size_t)b * OUTS;
#pragma unroll 1
    for (int s = 0; s < OUTS; ++s) {
        float4 xs = gru_step<true>(sw, hc, hx, tid, px);
        float4 x = make_float4(xs.x + px.x, xs.y + px.y, xs.z + px.z, xs.w + px.w);
        px = x;
        outb[s] = make_float4(x.x + off.x, x.y + off.y, x.z + off.z, x.w + off.w);
        float* tmp = hc; hc = hx; hx = tmp;
    }
}

extern "C" void kernel_launch(void* const* d_in, const int* in_sizes, int n_in,
                              void* d_out, int out_size) {
    const float* seq     = (const float*)d_in[0];
    const float* enc_Wih = (const float*)d_in[1];
    const float* enc_Whh = (const float*)d_in[2];
    const float* enc_bih = (const float*)d_in[3];
    const float* enc_bhh = (const float*)d_in[4];
    const float* dec_Wih = (const float*)d_in[5];
    const float* dec_Whh = (const float*)d_in[6];
    const float* dec_bih = (const float*)d_in[7];
    const float* dec_bhh = (const float*)d_in[8];
    const float* lin_W   = (const float*)d_in[9];
    const float* lin_b   = (const float*)d_in[10];
    float* out = (float*)d_out;

    const size_t shmem = (SW_FLOATS + 2 * HBUF_FLOATS) * sizeof(float);  // ~185.5 KB
    cudaFuncSetAttribute(gru_encdec_kernel,
                         cudaFuncAttributeMaxDynamicSharedMemorySize, (int)shmem);

    const int B = 131072;
    gru_encdec_kernel<<<B / NT, NT, shmem>>>(seq, enc_Wih, enc_Whh, enc_bih, enc_bhh,
                                             dec_Wih, dec_Whh, dec_bih, dec_bhh,
                                             lin_W, lin_b, out);
}

// round 6
// speedup vs baseline: 3.2866x; 3.2866x over previous
#include <cuda_runtime.h>
#include <stdint.h>

#define NT 256          // threads per CTA (8 warps)
#define ROWS_PER_WARP 16
#define BATCH_PER_CTA 128
#define NTILES 24       // 192 gate cols / 8
#define KTILES 5        // K = 80 (64 h + 4 px + 1 bias + pad)

// ---- smem layout (bytes) ----
// bfrag: [2 mats][24 nt][5 kt][32 lanes] x uint4  = 122880
#define OFF_BF    0
#define OFF_WN4   122880            // float4 [2][64]  (Wih rows for n-gates)
#define OFF_BIHN  (OFF_WN4 + 2048)  // float  [2][64]
#define OFF_LINWT (OFF_BIHN + 512)  // float4 [64]   linWT[j] = lin_W[:,j]
#define OFF_LINB  (OFF_LINWT + 1024)
#define SMEM_TOTAL (OFF_LINB + 16)

// ---------------- helpers ----------------
__device__ __forceinline__ uint32_t f2bf(float f) {
    uint16_t u;
    asm("cvt.rn.bf16.f32 %0, %1;" : "=h"(u) : "f"(f));
    return (uint32_t)u;
}
__device__ __forceinline__ float bfval(uint32_t u16) {
    return __uint_as_float(u16 << 16);
}
__device__ __forceinline__ float bfhi(uint32_t u32) {   // high half of packed pair
    return __uint_as_float(u32 & 0xffff0000u);
}
__device__ __forceinline__ float bflo(uint32_t u32) {   // low half
    return __uint_as_float(u32 << 16);
}
// pack two floats -> bf16x2 hi part and residual lo part
__device__ __forceinline__ void split2(float va, float vb, uint32_t& hi, uint32_t& lo) {
    uint32_t ha = f2bf(va), hb = f2bf(vb);
    uint32_t la = f2bf(va - bfval(ha)), lb = f2bf(vb - bfval(hb));
    hi = ha | (hb << 16);
    lo = la | (lb << 16);
}
__device__ __forceinline__ float fex2(float x) {
    float r;
    asm("ex2.approx.f32 %0, %1;" : "=f"(r) : "f"(x));
    return r;
}
__device__ __forceinline__ float frcp(float x) {
    float r;
    asm("rcp.approx.f32 %0, %1;" : "=f"(r) : "f"(x));
    return r;
}
__device__ __forceinline__ float fsigmoid(float x) {
    return frcp(1.0f + fex2(-1.4426950408889634f * x));
}
__device__ __forceinline__ float ftanh(float x) {
    float a = fabsf(x);
    float t = 1.0f - 2.0f * frcp(fex2(2.8853900817779268f * a) + 1.0f);
    return copysignf(t, x);
}
__device__ __forceinline__ void mma16816(float* d, const uint32_t* a,
                                         uint32_t b0, uint32_t b1) {
    asm volatile(
        "mma.sync.aligned.m16n8k16.row.col.f32.bf16.bf16.f32 "
        "{%0,%1,%2,%3}, {%4,%5,%6,%7}, {%8,%9}, {%0,%1,%2,%3};"
        : "+f"(d[0]), "+f"(d[1]), "+f"(d[2]), "+f"(d[3])
        : "r"(a[0]), "r"(a[1]), "r"(a[2]), "r"(a[3]), "r"(b0), "r"(b1));
}

// Fetch one element of the folded K=80 weight matrix W~[n][k].
__device__ __forceinline__ float wfold(const float* Whh, const float* Wih,
                                       const float* bih, const float* bhh,
                                       int n, int k) {
    if (k < 64) return Whh[n * 64 + k];
    if (k < 68) return (n < 128) ? Wih[n * 4 + (k - 64)] : 0.0f;
    if (k == 68) return (n < 128) ? (bih[n] + bhh[n]) : bhh[n];
    return 0.0f;
}

__global__ void __launch_bounds__(NT, 1)
gru_encdec_mma(const float* __restrict__ seq,
               const float* __restrict__ enc_Wih, const float* __restrict__ enc_Whh,
               const float* __restrict__ enc_bih, const float* __restrict__ enc_bhh,
               const float* __restrict__ dec_Wih, const float* __restrict__ dec_Whh,
               const float* __restrict__ dec_bih, const float* __restrict__ dec_bhh,
               const float* __restrict__ lin_W, const float* __restrict__ lin_b,
               float* __restrict__ out) {
    extern __shared__ char smem[];
    const int tid = threadIdx.x;
    const int warp = tid >> 5;
    const int lane = tid & 31;
    const int g = lane >> 2;     // row group 0..7
    const int tc = lane & 3;     // thread-in-group

    // ---------------- one-time build of fragment-packed weights ----------------
    uint4* bfr = (uint4*)(smem + OFF_BF);
    for (int idx = tid; idx < 2 * NTILES * KTILES * 32; idx += NT) {
        int li = idx & 31;
        int kt = (idx >> 5) % KTILES;
        int nt = (idx / (32 * KTILES)) % NTILES;
        int mat = idx / (32 * KTILES * NTILES);
        const float* Whh = mat ? dec_Whh : enc_Whh;
        const float* Wih = mat ? dec_Wih : enc_Wih;
        const float* bih = mat ? dec_bih : enc_bih;
        const float* bhh = mat ? dec_bhh : enc_bhh;
        int n = nt * 8 + (li >> 2);
        int k0 = kt * 16 + (li & 3) * 2;
        float v0 = wfold(Whh, Wih, bih, bhh, n, k0);
        float v1 = wfold(Whh, Wih, bih, bhh, n, k0 + 1);
        float v2 = wfold(Whh, Wih, bih, bhh, n, k0 + 8);
        float v3 = wfold(Whh, Wih, bih, bhh, n, k0 + 9);
        uint4 q;
        split2(v0, v1, q.x, q.z);
        split2(v2, v3, q.y, q.w);
        bfr[idx] = q;
    }
    {   // epilogue tables
        float4* wn4 = (float4*)(smem + OFF_WN4);
        float* bihn = (float*)(smem + OFF_BIHN);
        float4* lwt = (float4*)(smem + OFF_LINWT);
        for (int j = tid; j < 64; j += NT) {
            wn4[j]      = ((const float4*)enc_Wih)[128 + j];
            wn4[64 + j] = ((const float4*)dec_Wih)[128 + j];
            bihn[j]      = enc_bih[128 + j];
            bihn[64 + j] = dec_bih[128 + j];
            lwt[j] = make_float4(lin_W[j], lin_W[64 + j], lin_W[128 + j], lin_W[192 + j]);
        }
        if (tid == 0) *(float4*)(smem + OFF_LINB) =
            make_float4(lin_b[0], lin_b[1], lin_b[2], lin_b[3]);
    }
    __syncthreads();

    // ---------------- per-warp state ----------------
    const int r0 = blockIdx.x * BATCH_PER_CTA + warp * ROWS_PER_WARP + g;
    const int r1 = r0 + 8;
    const float4* s0 = (const float4*)seq + (size_t)r0 * 51;
    const float4* s1 = (const float4*)seq + (size_t)r1 * 51;
    float4* o0 = (float4*)out + (size_t)r0 * 20;
    float4* o1 = (float4*)out + (size_t)r1 * 20;

    uint32_t aH[KTILES][4], aL[KTILES][4];
#pragma unroll
    for (int k = 0; k < KTILES; ++k)
#pragma unroll
        for (int r = 0; r < 4; ++r) { aH[k][r] = 0; aL[k][r] = 0; }

    float4 x0c = s0[0], x1c = s1[0];
    float4 px0 = make_float4(0, 0, 0, 0), px1 = px0;
    float4 off0, off1;
    const float4 lnb = *(const float4*)(smem + OFF_LINB);

#pragma unroll 1
    for (int t = 0; t < 70; ++t) {
        const bool dec = (t >= 50);
        if (!dec) {
            float4 xn0 = s0[t + 1], xn1 = s1[t + 1];
            px0 = make_float4(xn0.x - x0c.x, xn0.y - x0c.y, xn0.z - x0c.z, xn0.w - x0c.w);
            px1 = make_float4(xn1.x - x1c.x, xn1.y - x1c.y, xn1.z - x1c.z, xn1.w - x1c.w);
            x0c = xn0; x1c = xn1;
        }
        // build A kt=4: cols 64-67 = px, col 68 = 1.0 (bias), rest 0
        {
            float va0, vb0, va1, vb1;
            if (tc == 0)      { va0 = px0.x; vb0 = px0.y; va1 = px1.x; vb1 = px1.y; }
            else if (tc == 1) { va0 = px0.z; vb0 = px0.w; va1 = px1.z; vb1 = px1.w; }
            else if (tc == 2) { va0 = 1.0f; vb0 = 0.0f; va1 = 1.0f; vb1 = 0.0f; }
            else              { va0 = 0.0f; vb0 = 0.0f; va1 = 0.0f; vb1 = 0.0f; }
            split2(va0, vb0, aH[4][0], aL[4][0]);
            split2(va1, vb1, aH[4][1], aL[4][1]);
            aH[4][2] = aH[4][3] = aL[4][2] = aL[4][3] = 0;
        }

        // ---------------- GEMM: D[16 x 192] = A[16 x 80] * W~^T ----------------
        float d[NTILES][4];
#pragma unroll
        for (int nt = 0; nt < NTILES; ++nt)
#pragma unroll
            for (int c = 0; c < 4; ++c) d[nt][c] = 0.0f;

        const uint4* bm = bfr + (dec ? NTILES * KTILES * 32 : 0) + lane;
#pragma unroll
        for (int kt = 0; kt < KTILES; ++kt) {
#pragma unroll
            for (int nt = 0; nt < NTILES; ++nt) {
                uint4 b = bm[(nt * KTILES + kt) * 32];
                mma16816(d[nt], aH[kt], b.x, b.y);   // hi * hi
                mma16816(d[nt], aL[kt], b.x, b.y);   // lo * hi
                mma16816(d[nt], aH[kt], b.z, b.w);   // hi * lo
            }
        }

        // ---------------- epilogue (lane-local) ----------------
        const float4* wn4 = (const float4*)(smem + OFF_WN4) + (dec ? 64 : 0);
        const float* bihn = (const float*)(smem + OFF_BIHN) + (dec ? 64 : 0);
        const float4* lwt = (const float4*)(smem + OFF_LINWT);
        float la0x = 0, la0y = 0, la0z = 0, la0w = 0;
        float la1x = 0, la1y = 0, la1z = 0, la1w = 0;

#pragma unroll
        for (int nth = 0; nth < 8; ++nth) {
            const int kt = nth >> 1;
#pragma unroll
            for (int rp = 0; rp < 2; ++rp) {          // rp=0: row g, rp=1: row g+8
                const int areg = (nth & 1) * 2 + rp;
                uint32_t oh = aH[kt][areg], ol = aL[kt][areg];
                float hold0 = bflo(oh) + bflo(ol);
                float hold1 = bfhi(oh) + bfhi(ol);
                float hnew[2];
#pragma unroll
                for (int e = 0; e < 2; ++e) {
                    const int c = rp * 2 + e;
                    const int j = nth * 8 + tc * 2 + e;
                    float Dr = d[nth][c];
                    float Dz = d[8 + nth][c];
                    float Dn = d[16 + nth][c];        // gh_n (incl bhh_n)
                    float r = fsigmoid(Dr);
                    float z = fsigmoid(Dz);
                    float4 wn = wn4[j];
                    float4 px = rp ? px1 : px0;
                    float gin = bihn[j] + px.x * wn.x + px.y * wn.y +
                                px.z * wn.z + px.w * wn.w;
                    float n = ftanh(fmaf(r, Dn, gin));
                    float hold = e ? hold1 : hold0;
                    float h = n + z * (hold - n);
                    hnew[e] = h;
                    if (dec) {
                        float4 lw = lwt[j];
                        if (rp == 0) {
                            la0x = fmaf(h, lw.x, la0x); la0y = fmaf(h, lw.y, la0y);
                            la0z = fmaf(h, lw.z, la0z); la0w = fmaf(h, lw.w, la0w);
                        } else {
                            la1x = fmaf(h, lw.x, la1x); la1y = fmaf(h, lw.y, la1y);
                            la1z = fmaf(h, lw.z, la1z); la1w = fmaf(h, lw.w, la1w);
                        }
                    }
                }
                split2(hnew[0], hnew[1], aH[kt][areg], aL[kt][areg]);
            }
        }

        if (dec) {
            // reduce lin partials over the 4 lanes of each row group (tc dim)
#pragma unroll
            for (int m = 1; m <= 2; m <<= 1) {
                la0x += __shfl_xor_sync(0xffffffffu, la0x, m);
                la0y += __shfl_xor_sync(0xffffffffu, la0y, m);
                la0z += __shfl_xor_sync(0xffffffffu, la0z, m);
                la0w += __shfl_xor_sync(0xffffffffu, la0w, m);
                la1x += __shfl_xor_sync(0xffffffffu, la1x, m);
                la1y += __shfl_xor_sync(0xffffffffu, la1y, m);
                la1z += __shfl_xor_sync(0xffffffffu, la1z, m);
                la1w += __shfl_xor_sync(0xffffffffu, la1w, m);
            }
            float4 x0 = make_float4(la0x + lnb.x + px0.x, la0y + lnb.y + px0.y,
                                    la0z + lnb.z + px0.z, la0w + lnb.w + px0.w);
            float4 x1 = make_float4(la1x + lnb.x + px1.x, la1y + lnb.y + px1.y,
                                    la1z + lnb.z + px1.z, la1w + lnb.w + px1.w);
            px0 = x0; px1 = x1;
            if (tc == 0) {
                o0[t - 50] = make_float4(x0.x + off0.x, x0.y + off0.y,
                                         x0.z + off0.z, x0.w + off0.w);
                o1[t - 50] = make_float4(x1.x + off1.x, x1.y + off1.y,
                                         x1.z + off1.z, x1.w + off1.w);
            }
        } else if (t == 49) {
            off0 = x0c;   // input_seq[:, 50, :]
            off1 = x1c;
        }
    }
}

extern "C" void kernel_launch(void* const* d_in, const int* in_sizes, int n_in,
                              void* d_out, int out_size) {
    const float* seq     = (const float*)d_in[0];
    const float* enc_Wih = (const float*)d_in[1];
    const float* enc_Whh = (const float*)d_in[2];
    const float* enc_bih = (const float*)d_in[3];
    const float* enc_bhh = (const float*)d_in[4];
    const float* dec_Wih = (const float*)d_in[5];
    const float* dec_Whh = (const float*)d_in[6];
    const float* dec_bih = (const float*)d_in[7];
    const float* dec_bhh = (const float*)d_in[8];
    const float* lin_W   = (const float*)d_in[9];
    const float* lin_b   = (const float*)d_in[10];
    float* out = (float*)d_out;

    cudaFuncSetAttribute(gru_encdec_mma,
                         cudaFuncAttributeMaxDynamicSharedMemorySize, SMEM_TOTAL);

    const int B = 131072;
    gru_encdec_mma<<<B / BATCH_PER_CTA, NT, SMEM_TOTAL>>>(
        seq, enc_Wih, enc_Whh, enc_bih, enc_bhh,
        dec_Wih, dec_Whh, dec_bih, dec_bhh, lin_W, lin_b, out);
}